// round 5
// baseline (speedup 1.0000x reference)
#include <cuda_runtime.h>

#define Bn 256
#define Sn 64
#define Dn 64
#define Fn 10
#define NCn 10
#define Pf 2016.0f
#define NT 512

// float-offsets into dynamic smem
#define OFF_E    0        // 64x64
#define OFF_U    4096     // 64x64
#define OFF_V    8192     // 64x64
#define OFF_FH   12288    // 64x64
#define OFF_W0   16384    // 65x64 staging buf 0 (W1a, then fw1)
#define OFF_W1   20544    // 65x64 staging buf 1 (W1b); aliased as Hpart[32x64] after V gemm
#define OFF_CW2  24704    // 64x10
#define OFF_FW2T 25344    // 10x64 (transposed freq_w2)
#define OFF_CC   25984    // 10x64
#define OFF_FR   26624    // 64
#define OFF_SID  26688    // 64 (int)
#define OFF_HSUM 26752    // 64
#define OFF_CSUM 26816    // 16
#define OFF_DIST 26832    // 64x10
#define SMEM_FLOATS 27472 // 109,888 bytes -> 2 CTAs/SM fit

__device__ __forceinline__ void gemm2x4(const float* __restrict__ sm, int woff,
                                        int s0, int dblk, float acc[2][4]) {
    const float4* E4 = (const float4*)(sm + OFF_E);
    const float4* W4 = (const float4*)(sm + woff);
#pragma unroll 4
    for (int kk = 0; kk < 16; ++kk) {
        float4 w0 = W4[(4 * kk + 0) * 16 + dblk];
        float4 w1 = W4[(4 * kk + 1) * 16 + dblk];
        float4 w2 = W4[(4 * kk + 2) * 16 + dblk];
        float4 w3 = W4[(4 * kk + 3) * 16 + dblk];
#pragma unroll
        for (int si = 0; si < 2; ++si) {
            float4 e = E4[(s0 + si) * 16 + kk];
            acc[si][0] += e.x * w0.x + e.y * w1.x + e.z * w2.x + e.w * w3.x;
            acc[si][1] += e.x * w0.y + e.y * w1.y + e.z * w2.y + e.w * w3.y;
            acc[si][2] += e.x * w0.z + e.y * w1.z + e.z * w2.z + e.w * w3.z;
            acc[si][3] += e.x * w0.w + e.y * w1.w + e.z * w2.w + e.w * w3.w;
        }
    }
}

__global__ __launch_bounds__(NT, 2)
void cate_enc_kernel(const int* __restrict__ ids, const float* __restrict__ table,
                     const float* __restrict__ cw1, const float* __restrict__ cb1,
                     const float* __restrict__ cw2g, const float* __restrict__ cb2,
                     const float* __restrict__ fw1, const float* __restrict__ fb1,
                     const float* __restrict__ fw2g, const float* __restrict__ fb2,
                     const float* __restrict__ ccg, const float* __restrict__ catf,
                     const float* __restrict__ tot, float* __restrict__ out) {
    extern __shared__ float sm[];
    const int t = threadIdx.x;
    const int b = blockIdx.x;

    const int dblk = t & 15;          // 0..15 (float4 column)
    const int sp   = t >> 4;          // 0..31
    const int s0   = sp * 2;

    // ---------- ph0: ids/freqs, stage W1a + small weights ----------
    if (t < Sn) {
        int id = ids[b * Sn + t];
        ((int*)(sm + OFF_SID))[t] = id;
        sm[OFF_FR + t] = catf[id] / tot[0];
    }
    {
        float4* W0 = (float4*)(sm + OFF_W0);
        const float4* g4 = (const float4*)cw1;       // rows 0..63 = W1a
        W0[t]       = g4[t];
        W0[t + 512] = g4[t + 512];
        if (t < 160) {
            ((float4*)(sm + OFF_CW2))[t] = ((const float4*)cw2g)[t];
            ((float4*)(sm + OFF_CC))[t]  = ((const float4*)ccg)[t];
        }
        // fw2 transposed: fw2T[f*64+d] = fw2[d*10+f]
        for (int i = t; i < Dn * Fn; i += NT) {
            int f = i >> 6, d = i & 63;
            sm[OFF_FW2T + i] = fw2g[d * Fn + f];
        }
    }
    __syncthreads();

    // ---------- ph1: gather E (needs sid) + stage W1b concurrently ----------
    {
        float4* E4 = (float4*)(sm + OFF_E);
        const float4* T4 = (const float4*)table;
        const int* sid = (const int*)(sm + OFF_SID);
#pragma unroll
        for (int c = 0; c < 2; ++c) {
            int lin = t + NT * c;
            int s = lin >> 4, q = lin & 15;
            E4[lin] = T4[sid[s] * 16 + q];
        }
        float4* W1 = (float4*)(sm + OFF_W1);
        const float4* g4 = (const float4*)cw1;       // rows 64..127 = W1b
        W1[t]       = g4[1024 + t];
        W1[t + 512] = g4[1024 + t + 512];
    }
    __syncthreads();

    // ---------- ph2: U = E @ W1a + b1 ----------
    {
        float acc[2][4] = {};
        gemm2x4(sm, OFF_W0, s0, dblk, acc);
        float4 bv = ((const float4*)cb1)[dblk];
        float4* U4 = (float4*)(sm + OFF_U);
#pragma unroll
        for (int si = 0; si < 2; ++si) {
            float4 o;
            o.x = acc[si][0] + bv.x; o.y = acc[si][1] + bv.y;
            o.z = acc[si][2] + bv.z; o.w = acc[si][3] + bv.w;
            U4[(s0 + si) * 16 + dblk] = o;
        }
    }
    __syncthreads();

    // ---------- ph3: V = E @ W1b ; stage fw1 -> W0 concurrently ----------
    {
        float4* W0 = (float4*)(sm + OFF_W0);
        const float4* g4 = (const float4*)fw1;       // 65 rows = 1040 float4
        W0[t]       = g4[t];
        W0[t + 512] = g4[t + 512];
        if (t < 16) W0[1024 + t] = g4[1024 + t];
    }
    {
        float acc[2][4] = {};
        gemm2x4(sm, OFF_W1, s0, dblk, acc);
        float4* V4 = (float4*)(sm + OFF_V);
#pragma unroll
        for (int si = 0; si < 2; ++si) {
            float4 o;
            o.x = acc[si][0]; o.y = acc[si][1]; o.z = acc[si][2]; o.w = acc[si][3];
            V4[(s0 + si) * 16 + dblk] = o;
        }
    }
    __syncthreads();

    // ---------- ph4: FH gemm ; pair-sum (Hpart aliases W1) ; distances ----------
    {   // FH = relu(E@fw1[:64] + fr*fw1[64] + fb1)
        float acc[2][4] = {};
        gemm2x4(sm, OFF_W0, s0, dblk, acc);
        float4 fbv = ((const float4*)fb1)[dblk];
        float4 wl  = ((const float4*)(sm + OFF_W0 + 64 * Dn))[dblk];
        float4* FH4 = (float4*)(sm + OFF_FH);
#pragma unroll
        for (int si = 0; si < 2; ++si) {
            float fq = sm[OFF_FR + s0 + si];
            float4 o;
            o.x = fmaxf(acc[si][0] + fq * wl.x + fbv.x, 0.f);
            o.y = fmaxf(acc[si][1] + fq * wl.y + fbv.y, 0.f);
            o.z = fmaxf(acc[si][2] + fq * wl.z + fbv.z, 0.f);
            o.w = fmaxf(acc[si][3] + fq * wl.w + fbv.w, 0.f);
            FH4[(s0 + si) * 16 + dblk] = o;
        }
    }
    {   // pair sum: thread (q=sp, dquad=dblk) owns i=q and i=63-q -> 63 iters, balanced
        const float4* U4 = (const float4*)(sm + OFF_U);
        const float4* V4 = (const float4*)(sm + OFF_V);
        const int q = sp;
        float4 a = {0.f, 0.f, 0.f, 0.f};
        float4 u1 = U4[q * 16 + dblk];
#pragma unroll 4
        for (int j = q + 1; j < Sn; ++j) {
            float4 v = V4[j * 16 + dblk];
            a.x += fmaxf(u1.x + v.x, 0.f);
            a.y += fmaxf(u1.y + v.y, 0.f);
            a.z += fmaxf(u1.z + v.z, 0.f);
            a.w += fmaxf(u1.w + v.w, 0.f);
        }
        float4 u2 = U4[(63 - q) * 16 + dblk];
#pragma unroll 4
        for (int j = Sn - q; j < Sn; ++j) {
            float4 v = V4[j * 16 + dblk];
            a.x += fmaxf(u2.x + v.x, 0.f);
            a.y += fmaxf(u2.y + v.y, 0.f);
            a.z += fmaxf(u2.z + v.z, 0.f);
            a.w += fmaxf(u2.w + v.w, 0.f);
        }
        ((float4*)(sm + OFF_W1))[q * 16 + dblk] = a;   // Hpart[q][d]
    }
    {   // distances: 640 items (s,c), fused |e|^2,|c|^2,dot
        const float4* E4 = (const float4*)(sm + OFF_E);
        const float4* C4 = (const float4*)(sm + OFF_CC);
        for (int it = t; it < Sn * NCn; it += NT) {
            int s = it / (unsigned)NCn, c = it - s * NCn;
            float dot = 0.f, e2 = 0.f, c2 = 0.f;
#pragma unroll 4
            for (int kk = 0; kk < 16; ++kk) {
                float4 e = E4[s * 16 + kk];
                float4 cv = C4[c * 16 + kk];
                dot += e.x * cv.x + e.y * cv.y + e.z * cv.z + e.w * cv.w;
                e2  += e.x * e.x + e.y * e.y + e.z * e.z + e.w * e.w;
                c2  += cv.x * cv.x + cv.y * cv.y + cv.z * cv.z + cv.w * cv.w;
            }
            float d2 = e2 + c2 - 2.f * dot;
            sm[OFF_DIST + it] = sqrtf(fmaxf(d2, 0.f));
        }
    }
    __syncthreads();

    // ---------- ph5: softmax (t<64) ; Hsum (t in [64,128)) ----------
    if (t < Sn) {
        float* dr = sm + OFF_DIST + t * NCn;
        float mn = dr[0];
#pragma unroll
        for (int c = 1; c < NCn; ++c) mn = fminf(mn, dr[c]);
        float e[NCn]; float ssum = 0.f;
#pragma unroll
        for (int c = 0; c < NCn; ++c) { e[c] = __expf(mn - dr[c]); ssum += e[c]; }
        float inv = 1.f / ssum;
#pragma unroll
        for (int c = 0; c < NCn; ++c) dr[c] = e[c] * inv;
    } else if (t < 2 * Sn) {
        int d = t - Sn;
        const float* Hp = sm + OFF_W1;
        float s = 0.f;
#pragma unroll 8
        for (int q = 0; q < 32; ++q) s += Hp[q * Dn + d];
        sm[OFF_HSUM + d] = s;
    }
    __syncthreads();

    // ---------- ph6: csum (t<10) ----------
    if (t < NCn) {
        float s = 0.f;
#pragma unroll 8
        for (int d = 0; d < Dn; ++d) s += sm[OFF_HSUM + d] * sm[OFF_CW2 + d * Fn + t];
        sm[OFF_CSUM + t] = s + Pf * cb2[t];
    }
    __syncthreads();

    // ---------- ph7: final output ----------
    const float invP = 1.f / (Pf + 2.f);
    const float4* FH4 = (const float4*)(sm + OFF_FH);
    const float4* W2T = (const float4*)(sm + OFF_FW2T);
    for (int it = t; it < Sn * Fn; it += NT) {
        int s = it / (unsigned)Fn, f = it - s * Fn;
        float ff = 0.f;
#pragma unroll 4
        for (int kk = 0; kk < 16; ++kk) {
            float4 h = FH4[s * 16 + kk];
            float4 w = W2T[f * 16 + kk];
            ff += h.x * w.x + h.y * w.y + h.z * w.z + h.w * w.w;
        }
        out[b * (Sn * Fn) + it] = (ff + fb2[f] + sm[OFF_CSUM + f] + sm[OFF_DIST + it]) * invP;
    }
}

extern "C" void kernel_launch(void* const* d_in, const int* in_sizes, int n_in,
                              void* d_out, int out_size) {
    const int*   ids  = (const int*)d_in[0];
    const float* tab  = (const float*)d_in[1];
    const float* cw1  = (const float*)d_in[2];
    const float* cb1  = (const float*)d_in[3];
    const float* cw2  = (const float*)d_in[4];
    const float* cb2  = (const float*)d_in[5];
    const float* fw1  = (const float*)d_in[6];
    const float* fb1  = (const float*)d_in[7];
    const float* fw2  = (const float*)d_in[8];
    const float* fb2  = (const float*)d_in[9];
    const float* cc   = (const float*)d_in[10];
    const float* catf = (const float*)d_in[11];
    const float* tot  = (const float*)d_in[12];
    float* out = (float*)d_out;

    cudaFuncSetAttribute(cate_enc_kernel,
                         cudaFuncAttributeMaxDynamicSharedMemorySize,
                         SMEM_FLOATS * (int)sizeof(float));
    cate_enc_kernel<<<Bn, NT, SMEM_FLOATS * sizeof(float)>>>(
        ids, tab, cw1, cb1, cw2, cb2, fw1, fb1, fw2, fb2, cc, catf, tot, out);
}